// round 7
// baseline (speedup 1.0000x reference)
#include <cuda_runtime.h>
#include <math.h>

#define S_LEN 16
#define BSZ   64
#define NN    10000
#define LL    128
#define DMSG  129
#define DH    257
#define SCALE 0.08838834764831844f  // 1/sqrt(128)
#define TILE_N 50
#define NP    200                    // NN / TILE_N
#define XR    260                    // padded X rows (257 + 3 zero pad)
#define GR    512                    // packed gate rows

// ---------------- scratch --------------------------------------------------------
__device__ float g_mem[NN * LL];
__device__ int   g_dirty[NN];
__device__ float g_X[XR * 128];           // per-cell input columns (row-major, 128 cells)
__device__ float g_Gp[GR * XR];           // packed gate weights, rows padded to 260
__device__ float g_bias[GR];              // [0..255]=b_ih+b_hh, [256..383]=b_ih_n, [384..511]=b_hh_n
__device__ float g_gates[GR * 128];       // GEMM output
__device__ float g_ck[BSZ * DH];
__device__ float g_qbk[BSZ];
__device__ float g_memdot[NN];
__device__ float4 g_part[BSZ * NP];       // per (b,tile): {m, Z, V, pad}
__device__ float g_cv[DH];
__device__ float g_cvc;
__device__ float g_enc0[LL];

// ---------------- K0a: zero ------------------------------------------------------
__global__ void k_zero_mem() {
    int i = blockIdx.x * blockDim.x + threadIdx.x;
    if (i < NN * LL) g_mem[i] = 0.0f;
    if (i < NN) { g_memdot[i] = 0.0f; g_dirty[i] = 0; }
    if (i < XR * 128) g_X[i] = 0.0f;      // incl. zero pad rows 257..259
}

// ---------------- K0b: init (grid 64 x 288): pack Gp + misc ----------------------
__global__ void k_init(const float* __restrict__ Wv, const float* __restrict__ W_out,
                       const float* __restrict__ bv, const float* __restrict__ b_out,
                       const float* __restrict__ time_b,
                       const float* __restrict__ W_ih, const float* __restrict__ W_hh,
                       const float* __restrict__ b_ih, const float* __restrict__ b_hh) {
    int tid = threadIdx.x;
    // pack 8 rows of Gp per block
    int j0 = blockIdx.x * 8;
    for (int r = 0; r < 8; r++) {
        int j = j0 + r;
        for (int d = tid; d < XR; d += blockDim.x) {
            float v = 0.0f;
            if (j < 256) {
                if (d < DMSG) v = W_ih[j * DMSG + d];
                else if (d < 257) v = W_hh[j * LL + (d - DMSG)];
            } else if (j < 384) {
                if (d < DMSG) v = W_ih[j * DMSG + d];
            } else {
                if (d < LL) v = W_hh[(j - 128) * LL + d];
            }
            g_Gp[j * XR + d] = v;
        }
    }
    if (blockIdx.x == 0) {
        if (tid < DH) {
            float a = 0.0f;
            const float* wr = Wv + tid * LL;
            for (int l = 0; l < LL; l++) a = fmaf(wr[l], W_out[l], a);
            g_cv[tid] = a;
        }
        if (tid < LL) g_enc0[tid] = cosf(time_b[tid]);
        if (tid == 280) {
            float a = 0.0f;
            for (int l = 0; l < LL; l++) a = fmaf(bv[l], W_out[l], a);
            g_cvc = a + b_out[0];
        }
    }
    if (blockIdx.x == 1) {
        for (int j = tid; j < GR; j += blockDim.x) {
            float v;
            if (j < 256) v = b_ih[j] + b_hh[j];
            else if (j < 384) v = b_ih[j];           // b_ih[256 + (j-256)]
            else v = b_hh[j - 128];                  // b_hh[256 + (j-384)]
            g_bias[j] = v;
        }
    }
}

// ---------------- prep: build X column for cell c of step sp ---------------------
__device__ __forceinline__ void do_prep(
        int sp, int c, int tid,
        const float* __restrict__ x, const float* __restrict__ t,
        const int* __restrict__ src, const int* __restrict__ tgt,
        const float* __restrict__ time_w, const float* __restrict__ time_b) {
    int b = c & 63, is_t = c >> 6;
    int node = (is_t ? tgt : src)[sp * BSZ + b];
    long base = ((long)(sp * BSZ + b)) * NN + node;
    if (tid == 0) g_X[c] = x[base];
    if (tid < LL) {
        float tv = __ldg(t + base);
        g_X[(1 + tid) * 128 + c] = cosf(fmaf(tv, time_w[tid], time_b[tid]));
        g_X[(DMSG + tid) * 128 + c] = g_mem[node * LL + tid];
    }
}

__global__ void k_prep0(const float* __restrict__ x, const float* __restrict__ t,
                        const int* __restrict__ src, const int* __restrict__ tgt,
                        const float* __restrict__ time_w, const float* __restrict__ time_b) {
    do_prep(0, blockIdx.x, threadIdx.x, x, t, src, tgt, time_w, time_b);
}

// ---------------- GRU cell epilogue from gates column ----------------------------
__device__ __forceinline__ float gru_cell(int c, int j) {
    float srz = g_gates[j * 128 + c];
    float szz = g_gates[(128 + j) * 128 + c];
    float gin = g_gates[(256 + j) * 128 + c];
    float ghn = g_gates[(384 + j) * 128 + c];
    float h   = g_X[(DMSG + j) * 128 + c];
    float r = 1.0f / (1.0f + __expf(-(srz + g_bias[j])));
    float z = 1.0f / (1.0f + __expf(-(szz + g_bias[128 + j])));
    float n = tanhf(fmaf(r, ghn + g_bias[384 + j], gin + g_bias[256 + j]));
    return fmaf(z, h - n, n);
}

// ---------------- combine (64 threads): merge NP softmax partials ----------------
__device__ __forceinline__ void combine64(float* __restrict__ out, int cs, int b) {
    __shared__ float s_m[2], s_z[2], s_v[2];
    int tid = threadIdx.x;            // 64
    int lane = tid & 31, warp = tid >> 5;
    float m = -1e30f, Z = 0.0f, V = 0.0f;
    for (int i = tid; i < NP; i += 64) {
        float4 p = g_part[b * NP + i];
        if (p.x > m) {
            float sc = __expf(m - p.x);
            Z = fmaf(Z, sc, p.y);
            V = fmaf(V, sc, p.z);
            m = p.x;
        } else {
            float e = __expf(p.x - m);
            Z = fmaf(p.y, e, Z);
            V = fmaf(p.z, e, V);
        }
    }
#pragma unroll
    for (int o = 16; o; o >>= 1) {
        float om = __shfl_xor_sync(0xffffffffu, m, o);
        float oZ = __shfl_xor_sync(0xffffffffu, Z, o);
        float oV = __shfl_xor_sync(0xffffffffu, V, o);
        float M = fmaxf(m, om);
        float e1 = __expf(m - M), e2 = __expf(om - M);
        Z = fmaf(Z, e1, oZ * e2);
        V = fmaf(V, e1, oV * e2);
        m = M;
    }
    if (lane == 0) { s_m[warp] = m; s_z[warp] = Z; s_v[warp] = V; }
    __syncthreads();
    if (tid == 0) {
        float M = fmaxf(s_m[0], s_m[1]);
        float z = s_z[0] * __expf(s_m[0] - M) + s_z[1] * __expf(s_m[1] - M);
        float v = s_v[0] * __expf(s_m[0] - M) + s_v[1] * __expf(s_m[1] - M);
        out[cs * BSZ + b] = v / z + g_cvc;
    }
}

// ---------------- K1: GEMM gates = Gp @ X (blocks 0..63) + combine (64..127) -----
__global__ void __launch_bounds__(64) k_gemm_comb(float* __restrict__ out, int s) {
    if (blockIdx.x >= 64) {
        if (s >= 1) combine64(out, s - 1, blockIdx.x - 64);
        return;
    }
    if (s >= S_LEN) return;

    int w = blockIdx.x * 2 + (threadIdx.x >> 5);   // warp 0..127
    int lane = threadIdx.x & 31;
    int j0 = w * 4;                                 // 4 consecutive rows, same class
    int D4, xoff;
    if (j0 < 256)      { D4 = 65; xoff = 0; }       // full 257 (+pad 3)
    else if (j0 < 384) { D4 = 33; xoff = 0; }       // msg part (129, pad to 132)
    else               { D4 = 32; xoff = DMSG; }    // h part (128)

    const float4* gp0 = (const float4*)(g_Gp + (j0 + 0) * XR);
    const float4* gp1 = (const float4*)(g_Gp + (j0 + 1) * XR);
    const float4* gp2 = (const float4*)(g_Gp + (j0 + 2) * XR);
    const float4* gp3 = (const float4*)(g_Gp + (j0 + 3) * XR);
    const float4* xp  = (const float4*)(g_X + xoff * 128) + lane;

    float4 a0 = {0, 0, 0, 0}, a1 = {0, 0, 0, 0}, a2 = {0, 0, 0, 0}, a3 = {0, 0, 0, 0};

#pragma unroll 2
    for (int q = 0; q < D4; q++) {
        float4 w0 = __ldg(gp0 + q);
        float4 w1 = __ldg(gp1 + q);
        float4 w2 = __ldg(gp2 + q);
        float4 w3 = __ldg(gp3 + q);
        float4 x0 = __ldg(xp + (4 * q + 0) * 32);
        float4 x1 = __ldg(xp + (4 * q + 1) * 32);
        float4 x2 = __ldg(xp + (4 * q + 2) * 32);
        float4 x3 = __ldg(xp + (4 * q + 3) * 32);
#define F4(acc, ws) \
        acc.x = fmaf(ws.x, x0.x, acc.x); acc.y = fmaf(ws.x, x0.y, acc.y); \
        acc.z = fmaf(ws.x, x0.z, acc.z); acc.w = fmaf(ws.x, x0.w, acc.w); \
        acc.x = fmaf(ws.y, x1.x, acc.x); acc.y = fmaf(ws.y, x1.y, acc.y); \
        acc.z = fmaf(ws.y, x1.z, acc.z); acc.w = fmaf(ws.y, x1.w, acc.w); \
        acc.x = fmaf(ws.z, x2.x, acc.x); acc.y = fmaf(ws.z, x2.y, acc.y); \
        acc.z = fmaf(ws.z, x2.z, acc.z); acc.w = fmaf(ws.z, x2.w, acc.w); \
        acc.x = fmaf(ws.w, x3.x, acc.x); acc.y = fmaf(ws.w, x3.y, acc.y); \
        acc.z = fmaf(ws.w, x3.z, acc.z); acc.w = fmaf(ws.w, x3.w, acc.w);
        F4(a0, w0) F4(a1, w1) F4(a2, w2) F4(a3, w3)
#undef F4
    }
    ((float4*)(g_gates + (j0 + 0) * 128))[lane] = a0;
    ((float4*)(g_gates + (j0 + 1) * 128))[lane] = a1;
    ((float4*)(g_gates + (j0 + 2) * 128))[lane] = a2;
    ((float4*)(g_gates + (j0 + 3) * 128))[lane] = a3;
}

// ---------------- K2: update = epilogue+scatter (0..127) + qck (128..191) --------
__global__ void __launch_bounds__(256) k_update(
        const float* __restrict__ x, const int* __restrict__ src,
        const int* __restrict__ tgt,
        const float* __restrict__ Wq, const float* __restrict__ bq,
        const float* __restrict__ Wk, const float* __restrict__ bk, int s) {
    __shared__ int s_nodes[2 * BSZ];
    int tid = threadIdx.x;

    if (tid < 128)
        s_nodes[tid] = (tid < BSZ) ? src[s * BSZ + tid] : tgt[s * BSZ + (tid - BSZ)];
    __syncthreads();

    if (blockIdx.x < 128) {
        // ---- epilogue + scatter role ----
        __shared__ float s_red[4];
        int c = blockIdx.x;
        int my = s_nodes[c];
        bool loser = (tid < 128) && (tid > c) && (s_nodes[tid] == my);
        if (__syncthreads_or(loser)) return;
        if (tid < 128) {
            float v = gru_cell(c, tid);
            g_mem[my * LL + tid] = v;
            float a = v * g_cv[1 + tid];
#pragma unroll
            for (int o = 16; o; o >>= 1) a += __shfl_xor_sync(0xffffffffu, a, o);
            if ((tid & 31) == 0) s_red[tid >> 5] = a;
        }
        __syncthreads();
        if (tid == 0) {
            g_memdot[my] = s_red[0] + s_red[1] + s_red[2] + s_red[3];
            g_dirty[my] = 1;
        }
        return;
    }

    // ---- qck role ----
    __shared__ float s_th[DH];
    __shared__ float s_qp[2][LL];
    __shared__ float s_q[LL];
    __shared__ int s_win;
    int b = blockIdx.x - 128;
    int warp = tid >> 5, lane = tid & 31;
    int mynode = s_nodes[BSZ + b];
    if (tid == 0) s_win = BSZ + b;
    __syncthreads();
    if (tid < 128 && s_nodes[tid] == mynode) atomicMax(&s_win, tid);
    __syncthreads();
    int cwin = s_win;

    if (tid == 0) s_th[0] = x[((long)(s * BSZ + b)) * NN + mynode];
    if (tid < LL) {
        s_th[1 + tid] = gru_cell(cwin, tid);      // post-update memory of tgt node
        s_th[1 + LL + tid] = g_enc0[tid];
    }
    __syncthreads();
    {
        int l = tid & 127, half = tid >> 7;
        int d0 = half * 128, d1 = half ? DH : 128;
        float a0 = 0.f, a1 = 0.f, a2 = 0.f, a3 = 0.f;
        int d = d0;
        for (; d + 3 < d1; d += 4) {
            a0 = fmaf(s_th[d],     __ldg(Wq + (d    ) * LL + l), a0);
            a1 = fmaf(s_th[d + 1], __ldg(Wq + (d + 1) * LL + l), a1);
            a2 = fmaf(s_th[d + 2], __ldg(Wq + (d + 2) * LL + l), a2);
            a3 = fmaf(s_th[d + 3], __ldg(Wq + (d + 3) * LL + l), a3);
        }
        for (; d < d1; d++) a0 = fmaf(s_th[d], __ldg(Wq + d * LL + l), a0);
        s_qp[half][l] = (a0 + a1) + (a2 + a3);
    }
    __syncthreads();
    if (tid < LL) s_q[tid] = s_qp[0][tid] + s_qp[1][tid] + bq[tid];
    __syncthreads();

    for (int d = warp; d < DH; d += 8) {
        float a = 0.0f;
        const float* wr = Wk + d * LL;
#pragma unroll
        for (int ch = 0; ch < 4; ch++) a = fmaf(__ldg(wr + ch * 32 + lane), s_q[ch * 32 + lane], a);
#pragma unroll
        for (int o = 16; o; o >>= 1) a += __shfl_xor_sync(0xffffffffu, a, o);
        if (lane == 0) g_ck[b * DH + d] = SCALE * a;
    }
    if (tid == 0) {
        float a = 0.0f;
        for (int l = 0; l < LL; l++) a = fmaf(s_q[l], bk[l], a);
        g_qbk[b] = SCALE * a;
    }
}

// ---------------- K3: scores + online softmax partials + prep(s+1) ---------------
__global__ void __launch_bounds__(256) k_scores(
        const float* __restrict__ x, const float* __restrict__ t,
        const int* __restrict__ mask, const int* __restrict__ src,
        const int* __restrict__ tgt,
        const float* __restrict__ time_w, const float* __restrict__ time_b, int s) {
    int tid = threadIdx.x;
    if (blockIdx.y == 8) {                          // prep role for step s+1
        if (blockIdx.x < 128 && s + 1 < S_LEN)
            do_prep(s + 1, blockIdx.x, tid, x, t, src, tgt, time_w, time_b);
        return;
    }
    int warp = tid >> 5, lane = tid & 31;
    int n0 = blockIdx.x * TILE_N;
    int b = blockIdx.y * 8 + warp;
    long base = ((long)(s * BSZ + b)) * NN;

    // lane-staged row data
    int nA = n0 + lane;
    int nB = n0 + 32 + ((lane < 18) ? lane : 17);
    float tA = __ldg(t + base + nA),    tB = __ldg(t + base + nB);
    int   mA = __ldg(mask + base + nA), mB = __ldg(mask + base + nB);
    float xA = __ldg(x + base + nA),    xB = __ldg(x + base + nB);
    int   dA = g_dirty[nA],             dB = g_dirty[nB];
    float mdA = g_memdot[nA],           mdB = g_memdot[nB];

    float tw[4], tc[4], ckd[4], ckm[4], cvd[4];
#pragma unroll
    for (int j = 0; j < 4; j++) {
        int l = j * 32 + lane;
        tw[j]  = time_w[l];
        tc[j]  = time_b[l];
        ckd[j] = g_ck[b * DH + 1 + LL + l];
        ckm[j] = g_ck[b * DH + 1 + l];
        cvd[j] = g_cv[1 + LL + l];
    }
    float ck0 = g_ck[b * DH];
    float qbk = g_qbk[b];
    float cv0 = g_cv[0];

    float m = -1e30f, Z = 0.0f, V1 = 0.0f;
    float acc0 = 0.f, acc1 = 0.f, acc2 = 0.f, acc3 = 0.f;

#pragma unroll 2
    for (int r = 0; r < TILE_N; r++) {
        bool grpA = (r < 32);
        int idx = grpA ? r : (r - 32);
        int mr = __shfl_sync(0xffffffffu, grpA ? mA : mB, idx);
        if (!mr) continue;
        float tv = __shfl_sync(0xffffffffu, grpA ? tA : tB, idx);
        int dirty = __shfl_sync(0xffffffffu, grpA ? dA : dB, idx);

        float cw0 = __cosf(fmaf(tv, tw[0], tc[0]));
        float cw1 = __cosf(fmaf(tv, tw[1], tc[1]));
        float cw2 = __cosf(fmaf(tv, tw[2], tc[2]));
        float cw3 = __cosf(fmaf(tv, tw[3], tc[3]));
        float sp = ckd[0] * cw0;
        sp = fmaf(ckd[1], cw1, sp);
        sp = fmaf(ckd[2], cw2, sp);
        sp = fmaf(ckd[3], cw3, sp);
        if (dirty) {
            const float* mr_ = g_mem + (long)(n0 + r) * LL;
            sp = fmaf(ckm[0], __ldg(mr_ + lane), sp);
            sp = fmaf(ckm[1], __ldg(mr_ + 32 + lane), sp);
            sp = fmaf(ckm[2], __ldg(mr_ + 64 + lane), sp);
            sp = fmaf(ckm[3], __ldg(mr_ + 96 + lane), sp);
        }
#pragma unroll
        for (int o = 16; o; o >>= 1) sp += __shfl_xor_sync(0xffffffffu, sp, o);

        float xr  = __shfl_sync(0xffffffffu, grpA ? xA : xB, idx);
        float mdr = __shfl_sync(0xffffffffu, grpA ? mdA : mdB, idx);
        float sc = fmaf(ck0, xr, sp) + qbk;
        float val = fmaf(cv0, xr, mdr);

        if (sc > m) {
            float sca = __expf(m - sc);
            Z = fmaf(Z, sca, 1.0f);
            V1 = fmaf(V1, sca, val);
            acc0 = fmaf(acc0, sca, cw0);
            acc1 = fmaf(acc1, sca, cw1);
            acc2 = fmaf(acc2, sca, cw2);
            acc3 = fmaf(acc3, sca, cw3);
            m = sc;
        } else {
            float e = __expf(sc - m);
            Z += e;
            V1 = fmaf(e, val, V1);
            acc0 = fmaf(e, cw0, acc0);
            acc1 = fmaf(e, cw1, acc1);
            acc2 = fmaf(e, cw2, acc2);
            acc3 = fmaf(e, cw3, acc3);
        }
    }

    float w = cvd[0] * acc0;
    w = fmaf(cvd[1], acc1, w);
    w = fmaf(cvd[2], acc2, w);
    w = fmaf(cvd[3], acc3, w);
#pragma unroll
    for (int o = 16; o; o >>= 1) w += __shfl_xor_sync(0xffffffffu, w, o);

    if (lane == 0)
        g_part[b * NP + blockIdx.x] = make_float4(m, Z, V1 + w, 0.0f);
}

// ---------------- host -----------------------------------------------------------
extern "C" void kernel_launch(void* const* d_in, const int* in_sizes, int n_in,
                              void* d_out, int out_size) {
    const float* x       = (const float*)d_in[0];
    const float* t       = (const float*)d_in[1];
    const int*   src     = (const int*)d_in[2];
    const int*   tgt     = (const int*)d_in[3];
    const int*   mask    = (const int*)d_in[4];
    const float* time_w  = (const float*)d_in[5];
    const float* time_b  = (const float*)d_in[6];
    const float* W_ih    = (const float*)d_in[7];
    const float* W_hh    = (const float*)d_in[8];
    const float* b_ih    = (const float*)d_in[9];
    const float* b_hh    = (const float*)d_in[10];
    const float* Wq      = (const float*)d_in[11];
    const float* bq      = (const float*)d_in[12];
    const float* Wk      = (const float*)d_in[13];
    const float* bk      = (const float*)d_in[14];
    const float* Wv      = (const float*)d_in[15];
    const float* bv      = (const float*)d_in[16];
    const float* W_out   = (const float*)d_in[17];
    const float* b_out   = (const float*)d_in[18];
    float* out = (float*)d_out;

    k_zero_mem<<<(NN * LL + 255) / 256, 256>>>();
    k_init<<<64, 288>>>(Wv, W_out, bv, b_out, time_b, W_ih, W_hh, b_ih, b_hh);
    k_prep0<<<128, 128>>>(x, t, src, tgt, time_w, time_b);

    for (int s = 0; s < S_LEN; s++) {
        k_gemm_comb<<<128, 64>>>(out, s);
        k_update<<<192, 256>>>(x, src, tgt, Wq, bq, Wk, bk, s);
        k_scores<<<dim3(NP, 9), 256>>>(x, t, mask, src, tgt, time_w, time_b, s);
    }
    k_gemm_comb<<<128, 64>>>(out, S_LEN);   // final combine (gemm role no-op)
}